// round 5
// baseline (speedup 1.0000x reference)
#include <cuda_runtime.h>

// LinearTimeMMD fused: source/target [65536, 512] fp32 -> scalar.
// R1 streaming geometry (proven 6.7 TB/s): 1 pair per 128-thread block,
// 4 front-batched independent loads per thread. Fused deterministic
// fixed-point finish with parallel-exp epilogue on warp 0.

#define M2          32768
#define THREADS     128
#define F4_PER_ROW  128            // 512 floats / 4

// 2^40 fixed-point scale: |h| <= 10 -> |v| < 2^44; sum over 32768 < 2^59.
#define FP_SCALE    1099511627776.0

__device__ long long    g_acc   = 0;
__device__ unsigned int g_count = 0;

__global__ __launch_bounds__(THREADS, 16)
void mmd_fused_kernel(const float4* __restrict__ src,
                      const float4* __restrict__ tgt,
                      float* __restrict__ out)
{
    const int p = blockIdx.x;
    const int t = threadIdx.x;

    const size_t ro = (size_t)(2 * p) * F4_PER_ROW;   // row 2p   ("odd")
    const size_t re = ro + F4_PER_ROW;                // row 2p+1 ("even")

    // 4 independent front-batched loads (MLP_p1 = 4), each byte read once.
    const float4 xo = __ldg(src + ro + t);
    const float4 xe = __ldg(src + re + t);
    const float4 yo = __ldg(tgt + ro + t);
    const float4 ye = __ldg(tgt + re + t);

    float dxx = 0.f, dyy = 0.f, dxy = 0.f, dyx = 0.f;
    {
        float d;
        d = xo.x - xe.x; dxx = fmaf(d, d, dxx);
        d = xo.y - xe.y; dxx = fmaf(d, d, dxx);
        d = xo.z - xe.z; dxx = fmaf(d, d, dxx);
        d = xo.w - xe.w; dxx = fmaf(d, d, dxx);

        d = yo.x - ye.x; dyy = fmaf(d, d, dyy);
        d = yo.y - ye.y; dyy = fmaf(d, d, dyy);
        d = yo.z - ye.z; dyy = fmaf(d, d, dyy);
        d = yo.w - ye.w; dyy = fmaf(d, d, dyy);

        d = xo.x - ye.x; dxy = fmaf(d, d, dxy);
        d = xo.y - ye.y; dxy = fmaf(d, d, dxy);
        d = xo.z - ye.z; dxy = fmaf(d, d, dxy);
        d = xo.w - ye.w; dxy = fmaf(d, d, dxy);

        d = xe.x - yo.x; dyx = fmaf(d, d, dyx);
        d = xe.y - yo.y; dyx = fmaf(d, d, dyx);
        d = xe.z - yo.z; dyx = fmaf(d, d, dyx);
        d = xe.w - yo.w; dyx = fmaf(d, d, dyx);
    }

    // warp tree reduce (4 values)
    #pragma unroll
    for (int off = 16; off > 0; off >>= 1) {
        dxx += __shfl_xor_sync(0xffffffffu, dxx, off);
        dyy += __shfl_xor_sync(0xffffffffu, dyy, off);
        dxy += __shfl_xor_sync(0xffffffffu, dxy, off);
        dyx += __shfl_xor_sync(0xffffffffu, dyx, off);
    }

    __shared__ float4 warp_sums[THREADS / 32];   // 4 entries
    const int wid = t >> 5;
    const int lid = t & 31;
    if (lid == 0) warp_sums[wid] = make_float4(dxx, dyy, dxy, dyx);
    __syncthreads();
    // warps 1..3 are done after the barrier (they fall through to exit)

    if (wid == 0) {
        // broadcast LDS: every lane of warp 0 builds the 4 totals
        float4 s0 = warp_sums[0], s1 = warp_sums[1],
               s2 = warp_sums[2], s3 = warp_sums[3];
        dxx = s0.x + s1.x + s2.x + s3.x;
        dyy = s0.y + s1.y + s2.y + s3.y;
        dxy = s0.z + s1.z + s2.z + s3.z;
        dyx = s0.w + s1.w + s2.w + s3.w;

        // bw = sum/4 / KERNEL_MUL^(KERNEL_NUM/2) = sum/16
        const float bw = (dxx + dyy + dxy + dyx) * (1.0f / 16.0f);

        // lanes 0..19 each compute one signed exp term in parallel:
        //   kernel index k = lid>>2 (mult = 2^k), term = lid&3
        float h = 0.f;
        if (lid < 20) {
            const int term = lid & 3;
            const float mult = (float)(1 << (lid >> 2));
            const float inv  = 1.0f / (bw * mult + 1e-6f);
            float dsel = (term == 0) ? dxx : (term == 1) ? dyy
                       : (term == 2) ? dxy : dyx;
            h = expf(-dsel * inv);
            if (term >= 2) h = -h;
        }

        #pragma unroll
        for (int off = 16; off > 0; off >>= 1)
            h += __shfl_xor_sync(0xffffffffu, h, off);

        if (lid == 0) {
            long long v = (long long)llrint((double)h * FP_SCALE);
            atomicAdd((unsigned long long*)&g_acc, (unsigned long long)v);
            __threadfence();
            unsigned int done = atomicAdd(&g_count, 1u);
            if (done == M2 - 1) {
                __threadfence();   // acquire: see all other blocks' acc-adds
                long long acc = g_acc;
                out[0] = (float)(((double)acc / FP_SCALE) / (double)M2);
                // reset for next graph replay
                g_acc   = 0;
                g_count = 0;
                __threadfence();
            }
        }
    }
}

extern "C" void kernel_launch(void* const* d_in, const int* in_sizes, int n_in,
                              void* d_out, int out_size)
{
    const float4* src = (const float4*)d_in[0];
    const float4* tgt = (const float4*)d_in[1];
    float* out = (float*)d_out;

    mmd_fused_kernel<<<M2, THREADS>>>(src, tgt, out);
}

// round 6
// speedup vs baseline: 1.0484x; 1.0484x over previous
#include <cuda_runtime.h>

// LinearTimeMMD fused single-wave persistent kernel.
// source/target [65536, 512] fp32 -> scalar. m2 = 32768 pairs.
// 1024 blocks x 8 warps = 8192 warps, each handles EXACTLY 4 pairs
// (no wave quantization: all blocks resident in one wave).
// Warp-per-pair streaming: 32 threads x 4 float4 per row.
// Parallel-exp epilogue (lanes 0-19), per-lane h accumulation across the
// loop, one warp-reduce at end, one fixed-point int64 atomic per block.

#define M2             32768
#define BLOCKS         1024
#define WARPS_PER_BLK  8
#define THREADS        256
#define TOTAL_WARPS    (BLOCKS * WARPS_PER_BLK)     // 8192
#define PAIRS_PER_WARP (M2 / TOTAL_WARPS)           // 4
#define F4_PER_ROW     128                          // 512 floats / 4

// 2^40 fixed-point scale: |h| <= 10 -> per-warp |sum| < 2^46; total < 2^59.
#define FP_SCALE       1099511627776.0

__device__ long long    g_acc   = 0;
__device__ unsigned int g_count = 0;

__global__ __launch_bounds__(THREADS, 8)
void mmd_fused_kernel(const float4* __restrict__ src,
                      const float4* __restrict__ tgt,
                      float* __restrict__ out)
{
    const int t   = threadIdx.x;
    const int wid = t >> 5;
    const int lid = t & 31;
    const int gw  = blockIdx.x * WARPS_PER_BLK + wid;   // global warp id

    // per-lane h-term accumulator (lanes 0..19 active in epilogue)
    float hacc = 0.f;

    // precompute this lane's epilogue constants
    const int   term    = lid & 3;                      // 0:dxx 1:dyy 2:dxy 3:dyx
    const float mult    = (float)(1 << (lid >> 2));     // 2^k, k = lid/4
    const float signf   = (term >= 2) ? -1.f : 1.f;

    #pragma unroll
    for (int it = 0; it < PAIRS_PER_WARP; ++it) {
        const int p = gw + it * TOTAL_WARPS;
        const size_t ro = (size_t)(2 * p) * F4_PER_ROW;   // row 2p
        const size_t re = ro + F4_PER_ROW;                // row 2p+1

        // 4 independent front-batched streaming loads per lane
        const float4 xo = __ldcs(src + ro + lid);
        const float4 xe = __ldcs(src + re + lid);
        const float4 yo = __ldcs(tgt + ro + lid);
        const float4 ye = __ldcs(tgt + re + lid);
        const float4 xo2 = __ldcs(src + ro + lid + 32);
        const float4 xe2 = __ldcs(src + re + lid + 32);
        const float4 yo2 = __ldcs(tgt + ro + lid + 32);
        const float4 ye2 = __ldcs(tgt + re + lid + 32);
        const float4 xo3 = __ldcs(src + ro + lid + 64);
        const float4 xe3 = __ldcs(src + re + lid + 64);
        const float4 yo3 = __ldcs(tgt + ro + lid + 64);
        const float4 ye3 = __ldcs(tgt + re + lid + 64);
        const float4 xo4 = __ldcs(src + ro + lid + 96);
        const float4 xe4 = __ldcs(src + re + lid + 96);
        const float4 yo4 = __ldcs(tgt + ro + lid + 96);
        const float4 ye4 = __ldcs(tgt + re + lid + 96);

        float dxx = 0.f, dyy = 0.f, dxy = 0.f, dyx = 0.f;
        {
            float d;
            #define ACC4(A, B, ACCV) \
                d = A.x - B.x; ACCV = fmaf(d, d, ACCV); \
                d = A.y - B.y; ACCV = fmaf(d, d, ACCV); \
                d = A.z - B.z; ACCV = fmaf(d, d, ACCV); \
                d = A.w - B.w; ACCV = fmaf(d, d, ACCV);

            ACC4(xo,  xe,  dxx)  ACC4(xo2, xe2, dxx)
            ACC4(xo3, xe3, dxx)  ACC4(xo4, xe4, dxx)
            ACC4(yo,  ye,  dyy)  ACC4(yo2, ye2, dyy)
            ACC4(yo3, ye3, dyy)  ACC4(yo4, ye4, dyy)
            ACC4(xo,  ye,  dxy)  ACC4(xo2, ye2, dxy)
            ACC4(xo3, ye3, dxy)  ACC4(xo4, ye4, dxy)
            ACC4(xe,  yo,  dyx)  ACC4(xe2, yo2, dyx)
            ACC4(xe3, yo3, dyx)  ACC4(xe4, yo4, dyx)
            #undef ACC4
        }

        // warp tree reduce (4 values) -> all lanes hold totals
        #pragma unroll
        for (int off = 16; off > 0; off >>= 1) {
            dxx += __shfl_xor_sync(0xffffffffu, dxx, off);
            dyy += __shfl_xor_sync(0xffffffffu, dyy, off);
            dxy += __shfl_xor_sync(0xffffffffu, dxy, off);
            dyx += __shfl_xor_sync(0xffffffffu, dyx, off);
        }

        // parallel epilogue: lanes 0..19 each add one signed exp term
        if (lid < 20) {
            const float bw  = (dxx + dyy + dxy + dyx) * (1.0f / 16.0f);
            const float inv = 1.0f / (bw * mult + 1e-6f);
            const float dsel = (term == 0) ? dxx : (term == 1) ? dyy
                             : (term == 2) ? dxy : dyx;
            hacc = fmaf(signf, expf(-dsel * inv), hacc);
        }
    }

    // final warp reduce of h across lanes
    #pragma unroll
    for (int off = 16; off > 0; off >>= 1)
        hacc += __shfl_xor_sync(0xffffffffu, hacc, off);

    __shared__ long long h_fixed[WARPS_PER_BLK];
    if (lid == 0)
        h_fixed[wid] = (long long)llrint((double)hacc * FP_SCALE);
    __syncthreads();

    if (t == 0) {
        long long v = 0;
        #pragma unroll
        for (int w = 0; w < WARPS_PER_BLK; ++w) v += h_fixed[w];
        atomicAdd((unsigned long long*)&g_acc, (unsigned long long)v);

        __threadfence();
        unsigned int done = atomicAdd(&g_count, 1u);
        if (done == BLOCKS - 1) {
            __threadfence();   // acquire: all other blocks' adds visible
            long long acc = g_acc;
            out[0] = (float)(((double)acc / FP_SCALE) / (double)M2);
            // reset for next graph replay
            g_acc   = 0;
            g_count = 0;
            __threadfence();
        }
    }
}

extern "C" void kernel_launch(void* const* d_in, const int* in_sizes, int n_in,
                              void* d_out, int out_size)
{
    const float4* src = (const float4*)d_in[0];
    const float4* tgt = (const float4*)d_in[1];
    float* out = (float*)d_out;

    mmd_fused_kernel<<<BLOCKS, THREADS>>>(src, tgt, out);
}